// round 16
// baseline (speedup 1.0000x reference)
#include <cuda_runtime.h>

// R15 champion + __launch_bounds__(128, 14): regs capped 40 -> 36, which
// admits 14 CTAs/SM (56 warps static vs 48). Everything else identical.
//
// Each warp owns 32 rows = one contiguous 3200B span. cp.async.bulk (TMA)
// loads the span into smem and — once the mbarrier flips — bulk-stores it
// straight back out as the output (round trip is the identity when no
// reflection coefficient clips; BOUND=1-1e-16 rounds to 1.0f). The warps
// only run the division-free scaled Levinson detector; the 400MB HBM
// stream rides the async TMA engine. Both bulk ops carry an
// L2::evict_first hint (data streams exactly once). Clipped rows (rare to
// nonexistent) overwrite themselves after wait_group-ordering behind the
// bulk store.

#define M 24
#define ROW 25
#define WARPS_PER_BLK 4
#define THREADS (WARPS_PER_BLK * 32)
#define ROWS_PER_WARP 32
#define FLOATS_PER_WARP (ROWS_PER_WARP * ROW)          // 800
#define BYTES_PER_WARP  (FLOATS_PER_WARP * 4)          // 3200 (16B multiple)

__device__ __forceinline__ void mbar_wait(unsigned mb, unsigned parity)
{
    asm volatile(
        "{\n\t"
        ".reg .pred P1;\n\t"
        "LAB_WAIT%=:\n\t"
        "mbarrier.try_wait.parity.acquire.cta.shared::cta.b64 P1, [%0], %1, 0x989680;\n\t"
        "@P1 bra LAB_DONE%=;\n\t"
        "bra LAB_WAIT%=;\n\t"
        "LAB_DONE%=:\n\t"
        "}"
        :: "r"(mb), "r"(parity) : "memory");
}

__device__ __forceinline__ unsigned long long evict_first_policy()
{
    unsigned long long pol;
    asm("createpolicy.fractional.L2::evict_first.b64 %0, 1.0;" : "=l"(pol));
    return pol;
}

// Division-free scaled downward Levinson: u_i = c_i * D, D = prod(1-k^2).
// Returns max |k_m|; > 1 (or NaN from degenerate D) means clipping fires.
__device__ __forceinline__ float detector(const float* __restrict__ row)
{
    float u[M];
    #pragma unroll
    for (int i = 0; i < M; ++i) u[i] = row[i + 1];

    float D = 1.0f, maxa = 0.0f;
    #pragma unroll
    for (int m = M; m >= 2; --m) {
        float um = u[m - 1];
        float k  = um * __fdividef(1.0f, D);
        maxa = fmaxf(maxa, fabsf(k));
        D = fmaf(-k, um, D);                 // D *= (1 - k^2)
        #pragma unroll
        for (int i = 0; 2 * i <= m - 2; ++i) {
            int j = m - 2 - i;
            float ui = u[i];
            float uj = u[j];
            if (i < j) {
                u[i] = fmaf(-k, uj, ui);
                u[j] = fmaf(-k, ui, uj);
            } else {
                u[i] = fmaf(-k, ui, ui);
            }
        }
    }
    return fmaxf(maxa, fabsf(u[0] * __fdividef(1.0f, D)));   // k_1
}

// Exact per-row path: true divides, clamp, upward recursion, overwrite row.
__device__ __noinline__ void fixup_row(const float* __restrict__ srow,
                                       float* __restrict__ orow)
{
    float c[M];
    #pragma unroll
    for (int i = 0; i < M; ++i) c[i] = srow[i + 1];

    #pragma unroll
    for (int m = M; m >= 2; --m) {
        float k   = c[m - 1];
        float inv = __fdividef(1.0f, 1.0f - k * k);
        #pragma unroll
        for (int i = 0; 2 * i <= m - 2; ++i) {
            int j = m - 2 - i;
            float ci = c[i], cj = c[j];
            if (i < j) {
                c[i] = fmaf(-k, cj, ci) * inv;
                c[j] = fmaf(-k, ci, cj) * inv;
            } else {
                c[i] = fmaf(-k, ci, ci) * inv;
            }
        }
    }
    #pragma unroll
    for (int i = 0; i < M; ++i)
        c[i] = fminf(fmaxf(c[i], -1.0f), 1.0f);

    #pragma unroll
    for (int m = 2; m <= M; ++m) {
        float km = c[m - 1];
        #pragma unroll
        for (int i = 0; 2 * i <= m - 2; ++i) {
            int j = m - 2 - i;
            float ci = c[i], cj = c[j];
            if (i < j) {
                c[i] = fmaf(km, cj, ci);
                c[j] = fmaf(km, ci, cj);
            } else {
                c[i] = fmaf(km, ci, ci);
            }
        }
    }
    #pragma unroll
    for (int i = 0; i < M; ++i) orow[i + 1] = c[i];
    // orow[0] (gain K) already correct from the bulk copy
}

__global__ __launch_bounds__(THREADS, 14)
void lpc_stability_kernel(const float* __restrict__ in, float* __restrict__ out, int B)
{
    __shared__ float s[WARPS_PER_BLK * FLOATS_PER_WARP];    // 12.8 KB
    __shared__ unsigned long long mbar[WARPS_PER_BLK];

    const int wid  = threadIdx.x >> 5;
    const int lane = threadIdx.x & 31;
    const long long wg = (long long)blockIdx.x * WARPS_PER_BLK + wid;
    const long long rbase = wg * ROWS_PER_WARP;
    if (rbase >= B) return;                    // warp-uniform exit
    const int nrows = min((long long)ROWS_PER_WARP, B - rbase);

    float* ws = s + wid * FLOATS_PER_WARP;
    const float* gsrc = in  + rbase * ROW;
    float*       gdst = out + rbase * ROW;
    unsigned s_addr = (unsigned)__cvta_generic_to_shared(ws);
    unsigned mb     = (unsigned)__cvta_generic_to_shared(&mbar[wid]);

    if (nrows == ROWS_PER_WARP) {
        // ---- async load of this warp's 3200B span (evict-first in L2) ----
        if (lane == 0) {
            unsigned long long pol = evict_first_policy();
            asm volatile("mbarrier.init.shared.b64 [%0], %1;"
                         :: "r"(mb), "r"(1) : "memory");
            asm volatile("mbarrier.arrive.expect_tx.shared.b64 _, [%0], %1;"
                         :: "r"(mb), "r"((unsigned)BYTES_PER_WARP) : "memory");
            asm volatile("cp.async.bulk.shared::cluster.global.mbarrier::complete_tx::bytes.L2::cache_hint "
                         "[%0], [%1], %2, [%3], %4;"
                         :: "r"(s_addr), "l"(gsrc), "r"((unsigned)BYTES_PER_WARP),
                            "r"(mb), "l"(pol)
                         : "memory");
        }
        __syncwarp();              // init visible before other lanes wait
        mbar_wait(mb, 0);          // acquire: smem tile ready

        // ---- async out-copy (identity result), evict-first in L2 ----
        if (lane == 0) {
            unsigned long long pol = evict_first_policy();
            asm volatile("fence.proxy.async.shared::cta;" ::: "memory");
            asm volatile("cp.async.bulk.global.shared::cta.bulk_group.L2::cache_hint "
                         "[%0], [%1], %2, %3;"
                         :: "l"(gdst), "r"(s_addr), "r"((unsigned)BYTES_PER_WARP),
                            "l"(pol)
                         : "memory");
            asm volatile("cp.async.bulk.commit_group;" ::: "memory");
        }

        // ---- detector (runs concurrently with the bulk store) ----
        const float* row = ws + lane * ROW;
        float maxa = detector(row);

        unsigned clip = __ballot_sync(0xffffffffu, !(maxa <= 1.0f));
        if (clip) {
            if (lane == 0)
                asm volatile("cp.async.bulk.wait_group 0;" ::: "memory");
            __syncwarp();          // fixup STGs ordered after the bulk store
            if (!(maxa <= 1.0f))
                fixup_row(row, gdst + (long long)lane * ROW);
        }
    } else {
        // ---- generic tail (not hit for B = 2M): scalar copy + detect ----
        int nelem = nrows * ROW;
        for (int idx = lane; idx < nelem; idx += 32) {
            float v = gsrc[idx];
            gdst[idx] = v;
            ws[idx] = v;
        }
        __syncwarp();
        if (lane < nrows) {
            const float* row = ws + lane * ROW;
            if (!(detector(row) <= 1.0f))
                fixup_row(row, gdst + (long long)lane * ROW);
        }
    }
}

extern "C" void kernel_launch(void* const* d_in, const int* in_sizes, int n_in,
                              void* d_out, int out_size)
{
    const float* a = (const float*)d_in[0];
    float* out = (float*)d_out;
    int B = in_sizes[0] / ROW;
    long long nwarps = ((long long)B + ROWS_PER_WARP - 1) / ROWS_PER_WARP;
    int grid = (int)((nwarps + WARPS_PER_BLK - 1) / WARPS_PER_BLK);
    lpc_stability_kernel<<<grid, THREADS>>>(a, out, B);
}

// round 17
// speedup vs baseline: 1.0116x; 1.0116x over previous
#include <cuda_runtime.h>

// R15 champion with 64-thread CTAs (finest scheduling granularity).
// Each warp owns 32 rows = one contiguous 3200B span. cp.async.bulk (TMA)
// loads the span into smem and — once the mbarrier flips — bulk-stores it
// straight back out as the output (round trip is the identity when no
// reflection coefficient clips; BOUND=1-1e-16 rounds to 1.0f). The warps
// only run the division-free scaled Levinson detector (~40 regs, the
// proven pareto point: 32-reg caps spill, >40 kills occupancy); the 400MB
// HBM stream rides the async TMA engine. Both bulk ops carry an
// L2::evict_first hint (data streams exactly once). Clipped rows (rare to
// nonexistent) overwrite themselves after wait_group-ordering behind the
// bulk store.
// 64-thread CTAs: 25 CTAs/SM x 2 warps = 50 warps static, with CTA
// retire/replace in the finest chunks -> minimal warp-count sag across
// the ~10 grid waves (the mechanism that won R15 over R13).

#define M 24
#define ROW 25
#define WARPS_PER_BLK 2
#define THREADS (WARPS_PER_BLK * 32)
#define ROWS_PER_WARP 32
#define FLOATS_PER_WARP (ROWS_PER_WARP * ROW)          // 800
#define BYTES_PER_WARP  (FLOATS_PER_WARP * 4)          // 3200 (16B multiple)

__device__ __forceinline__ void mbar_wait(unsigned mb, unsigned parity)
{
    asm volatile(
        "{\n\t"
        ".reg .pred P1;\n\t"
        "LAB_WAIT%=:\n\t"
        "mbarrier.try_wait.parity.acquire.cta.shared::cta.b64 P1, [%0], %1, 0x989680;\n\t"
        "@P1 bra LAB_DONE%=;\n\t"
        "bra LAB_WAIT%=;\n\t"
        "LAB_DONE%=:\n\t"
        "}"
        :: "r"(mb), "r"(parity) : "memory");
}

__device__ __forceinline__ unsigned long long evict_first_policy()
{
    unsigned long long pol;
    asm("createpolicy.fractional.L2::evict_first.b64 %0, 1.0;" : "=l"(pol));
    return pol;
}

// Division-free scaled downward Levinson: u_i = c_i * D, D = prod(1-k^2).
// Returns max |k_m|; > 1 (or NaN from degenerate D) means clipping fires.
__device__ __forceinline__ float detector(const float* __restrict__ row)
{
    float u[M];
    #pragma unroll
    for (int i = 0; i < M; ++i) u[i] = row[i + 1];

    float D = 1.0f, maxa = 0.0f;
    #pragma unroll
    for (int m = M; m >= 2; --m) {
        float um = u[m - 1];
        float k  = um * __fdividef(1.0f, D);
        maxa = fmaxf(maxa, fabsf(k));
        D = fmaf(-k, um, D);                 // D *= (1 - k^2)
        #pragma unroll
        for (int i = 0; 2 * i <= m - 2; ++i) {
            int j = m - 2 - i;
            float ui = u[i];
            float uj = u[j];
            if (i < j) {
                u[i] = fmaf(-k, uj, ui);
                u[j] = fmaf(-k, ui, uj);
            } else {
                u[i] = fmaf(-k, ui, ui);
            }
        }
    }
    return fmaxf(maxa, fabsf(u[0] * __fdividef(1.0f, D)));   // k_1
}

// Exact per-row path: true divides, clamp, upward recursion, overwrite row.
__device__ __noinline__ void fixup_row(const float* __restrict__ srow,
                                       float* __restrict__ orow)
{
    float c[M];
    #pragma unroll
    for (int i = 0; i < M; ++i) c[i] = srow[i + 1];

    #pragma unroll
    for (int m = M; m >= 2; --m) {
        float k   = c[m - 1];
        float inv = __fdividef(1.0f, 1.0f - k * k);
        #pragma unroll
        for (int i = 0; 2 * i <= m - 2; ++i) {
            int j = m - 2 - i;
            float ci = c[i], cj = c[j];
            if (i < j) {
                c[i] = fmaf(-k, cj, ci) * inv;
                c[j] = fmaf(-k, ci, cj) * inv;
            } else {
                c[i] = fmaf(-k, ci, ci) * inv;
            }
        }
    }
    #pragma unroll
    for (int i = 0; i < M; ++i)
        c[i] = fminf(fmaxf(c[i], -1.0f), 1.0f);

    #pragma unroll
    for (int m = 2; m <= M; ++m) {
        float km = c[m - 1];
        #pragma unroll
        for (int i = 0; 2 * i <= m - 2; ++i) {
            int j = m - 2 - i;
            float ci = c[i], cj = c[j];
            if (i < j) {
                c[i] = fmaf(km, cj, ci);
                c[j] = fmaf(km, ci, cj);
            } else {
                c[i] = fmaf(km, ci, ci);
            }
        }
    }
    #pragma unroll
    for (int i = 0; i < M; ++i) orow[i + 1] = c[i];
    // orow[0] (gain K) already correct from the bulk copy
}

__global__ __launch_bounds__(THREADS, 24)
void lpc_stability_kernel(const float* __restrict__ in, float* __restrict__ out, int B)
{
    __shared__ float s[WARPS_PER_BLK * FLOATS_PER_WARP];    // 6.4 KB
    __shared__ unsigned long long mbar[WARPS_PER_BLK];

    const int wid  = threadIdx.x >> 5;
    const int lane = threadIdx.x & 31;
    const long long wg = (long long)blockIdx.x * WARPS_PER_BLK + wid;
    const long long rbase = wg * ROWS_PER_WARP;
    if (rbase >= B) return;                    // warp-uniform exit
    const int nrows = min((long long)ROWS_PER_WARP, B - rbase);

    float* ws = s + wid * FLOATS_PER_WARP;
    const float* gsrc = in  + rbase * ROW;
    float*       gdst = out + rbase * ROW;
    unsigned s_addr = (unsigned)__cvta_generic_to_shared(ws);
    unsigned mb     = (unsigned)__cvta_generic_to_shared(&mbar[wid]);

    if (nrows == ROWS_PER_WARP) {
        // ---- async load of this warp's 3200B span (evict-first in L2) ----
        if (lane == 0) {
            unsigned long long pol = evict_first_policy();
            asm volatile("mbarrier.init.shared.b64 [%0], %1;"
                         :: "r"(mb), "r"(1) : "memory");
            asm volatile("mbarrier.arrive.expect_tx.shared.b64 _, [%0], %1;"
                         :: "r"(mb), "r"((unsigned)BYTES_PER_WARP) : "memory");
            asm volatile("cp.async.bulk.shared::cluster.global.mbarrier::complete_tx::bytes.L2::cache_hint "
                         "[%0], [%1], %2, [%3], %4;"
                         :: "r"(s_addr), "l"(gsrc), "r"((unsigned)BYTES_PER_WARP),
                            "r"(mb), "l"(pol)
                         : "memory");
        }
        __syncwarp();              // init visible before other lanes wait
        mbar_wait(mb, 0);          // acquire: smem tile ready

        // ---- async out-copy (identity result), evict-first in L2 ----
        if (lane == 0) {
            unsigned long long pol = evict_first_policy();
            asm volatile("fence.proxy.async.shared::cta;" ::: "memory");
            asm volatile("cp.async.bulk.global.shared::cta.bulk_group.L2::cache_hint "
                         "[%0], [%1], %2, %3;"
                         :: "l"(gdst), "r"(s_addr), "r"((unsigned)BYTES_PER_WARP),
                            "l"(pol)
                         : "memory");
            asm volatile("cp.async.bulk.commit_group;" ::: "memory");
        }

        // ---- detector (runs concurrently with the bulk store) ----
        const float* row = ws + lane * ROW;
        float maxa = detector(row);

        unsigned clip = __ballot_sync(0xffffffffu, !(maxa <= 1.0f));
        if (clip) {
            if (lane == 0)
                asm volatile("cp.async.bulk.wait_group 0;" ::: "memory");
            __syncwarp();          // fixup STGs ordered after the bulk store
            if (!(maxa <= 1.0f))
                fixup_row(row, gdst + (long long)lane * ROW);
        }
    } else {
        // ---- generic tail (not hit for B = 2M): scalar copy + detect ----
        int nelem = nrows * ROW;
        for (int idx = lane; idx < nelem; idx += 32) {
            float v = gsrc[idx];
            gdst[idx] = v;
            ws[idx] = v;
        }
        __syncwarp();
        if (lane < nrows) {
            const float* row = ws + lane * ROW;
            if (!(detector(row) <= 1.0f))
                fixup_row(row, gdst + (long long)lane * ROW);
        }
    }
}

extern "C" void kernel_launch(void* const* d_in, const int* in_sizes, int n_in,
                              void* d_out, int out_size)
{
    const float* a = (const float*)d_in[0];
    float* out = (float*)d_out;
    int B = in_sizes[0] / ROW;
    long long nwarps = ((long long)B + ROWS_PER_WARP - 1) / ROWS_PER_WARP;
    int grid = (int)((nwarps + WARPS_PER_BLK - 1) / WARPS_PER_BLK);
    lpc_stability_kernel<<<grid, THREADS>>>(a, out, B);
}